// round 8
// baseline (speedup 1.0000x reference)
#include <cuda_runtime.h>
#include <cuda_bf16.h>

typedef unsigned long long ull;

#define GMM_M   64
#define GMM_D   16
#define GMM_KP  8      // 16 dims = 8 f32x2 pairs
#define TPB     128
#define PPT     2
#define PPB     (TPB*PPT)

__device__ float4   g_P[GMM_M * GMM_KP];  // {A2k,A2k+1,B2k,B2k+1}, log2e-folded
__device__ float    g_C[GMM_M];           // log2e-folded constant
__device__ float    g_part[8192];
__device__ unsigned g_count = 0;

__device__ __forceinline__ ull pk2(float lo, float hi) {
    ull r; asm("mov.b64 %0, {%1, %2};" : "=l"(r) : "f"(lo), "f"(hi)); return r;
}
__device__ __forceinline__ void upk2(ull v, float &lo, float &hi) {
    asm("mov.b64 {%0, %1}, %2;" : "=f"(lo), "=f"(hi) : "l"(v));
}
__device__ __forceinline__ ull fma2(ull a, ull b, ull c) {
    ull r; asm("fma.rn.f32x2 %0, %1, %2, %3;" : "=l"(r) : "l"(a), "l"(b), "l"(c)); return r;
}
__device__ __forceinline__ float ex2f(float x) {
    float r; asm("ex2.approx.f32 %0, %1;" : "=f"(r) : "f"(x)); return r;
}

// ---------- kernel 1: parameter precompute (log2e folded) ----------
__global__ void __launch_bounds__(1024)
gmm_precompute(const float* __restrict__ wghts,
               const float* __restrict__ means,
               const float* __restrict__ dcovs) {
    __shared__ float sAf[GMM_M][GMM_D];
    __shared__ float sBf[GMM_M][GMM_D];
    const int tid = threadIdx.x;
    const int m = tid >> 4;
    const int d = tid & 15;
    const float LOG2E = 1.4426950408889634f;

    const float dc   = dcovs[m * GMM_D + d];
    const float mu   = means[m * GMM_D + d];
    const float prec = 1.0f / dc;
    sAf[m][d] = -0.5f * prec * LOG2E;
    sBf[m][d] = prec * mu * LOG2E;

    float cpart = (-0.5f * prec * mu * mu - 0.5f * __logf(dc)) * LOG2E;
    #pragma unroll
    for (int o = 8; o > 0; o >>= 1)
        cpart += __shfl_down_sync(0xffffffffu, cpart, o, 16);
    if (d == 0)
        g_C[m] = cpart + (__logf(wghts[m]) - 8.0f * __logf(6.283185307f)) * LOG2E;

    __syncthreads();
    if (tid < GMM_M * GMM_KP) {
        const int pm = tid >> 3;
        const int k  = tid & 7;
        g_P[tid] = make_float4(sAf[pm][2*k], sAf[pm][2*k+1],
                               sBf[pm][2*k], sBf[pm][2*k+1]);
    }
}

// ---------- kernel 2: main GMM E-step (non-persistent, 6 blocks/SM) ----------
__global__ void __launch_bounds__(TPB, 6)
gmm_main(const float* __restrict__ data,
         const float* __restrict__ means,
         float* __restrict__ out,
         int T, float invT) {
    __shared__ ulonglong2 sP[GMM_M * GMM_KP];
    __shared__ ulonglong2 sMu[GMM_M * 4];
    __shared__ float      sC[GMM_M];
    __shared__ float      sStage[PPB * 17];   // pitch-17 transpose, both PPT points
    __shared__ float      sRed[TPB];
    __shared__ bool       sLast;

    const int tid = threadIdx.x;
    {
        const float4* gp = (const float4*)g_P;
        float4*       dp = (float4*)sP;
        for (int i = tid; i < GMM_M * GMM_KP; i += TPB) dp[i] = gp[i];
        const float4* gm = (const float4*)means;
        float4*       dm = (float4*)sMu;
        for (int i = tid; i < GMM_M * 4; i += TPB) dm[i] = gm[i];
        if (tid < GMM_M) sC[tid] = g_C[tid];
    }
    __syncthreads();

    const int base = blockIdx.x * PPB;

    ull x[PPT][GMM_KP], num[PPT][GMM_KP];
    float like[PPT];

    #pragma unroll
    for (int j = 0; j < PPT; j++) {
        like[j] = 0.0f;
        const int t = base + tid + j * TPB;
        if (t < T) {
            const ulonglong2* dp2 = (const ulonglong2*)(data + (size_t)t * GMM_D);
            #pragma unroll
            for (int q = 0; q < 4; q++) {
                const ulonglong2 f = dp2[q];   // LDG.128, no repack
                x[j][2*q]   = f.x;
                x[j][2*q+1] = f.y;
            }
        } else {
            #pragma unroll
            for (int k = 0; k < GMM_KP; k++) x[j][k] = 0ULL;
        }
        #pragma unroll
        for (int k = 0; k < GMM_KP; k++) num[j][k] = 0ULL;
    }

    #pragma unroll 2
    for (int m = 0; m < GMM_M; m++) {
        ull acc[PPT];
        #pragma unroll
        for (int j = 0; j < PPT; j++) acc[j] = pk2(sC[m], 0.0f);

        #pragma unroll
        for (int k = 0; k < GMM_KP; k++) {
            const ulonglong2 ab = sP[m * GMM_KP + k];   // LDS.128 broadcast
            #pragma unroll
            for (int j = 0; j < PPT; j++) {
                const ull tt = fma2(ab.x, x[j][k], ab.y);
                acc[j] = fma2(tt, x[j][k], acc[j]);
            }
        }

        ull pb[PPT];
        #pragma unroll
        for (int j = 0; j < PPT; j++) {
            float lo, hi;
            upk2(acc[j], lo, hi);
            const float p = ex2f(lo + hi);
            like[j] += p;
            pb[j] = pk2(p, p);
        }

        #pragma unroll
        for (int kk = 0; kk < 4; kk++) {
            const ulonglong2 mm = sMu[m * 4 + kk];
            #pragma unroll
            for (int j = 0; j < PPT; j++) {
                num[j][2*kk]   = fma2(pb[j], mm.x, num[j][2*kk]);
                num[j][2*kk+1] = fma2(pb[j], mm.y, num[j][2*kk+1]);
            }
        }
    }

    float llsum = 0.0f;

    // epilogue: single-pass SMEM transpose for both points -> coalesced STG.32
    #pragma unroll
    for (int j = 0; j < PPT; j++) {
        const int tj = base + tid + j * TPB;
        const bool valid = (tj < T);
        const float inv = valid ? __fdividef(1.0f, like[j]) : 0.0f;
        if (valid) llsum += __logf(like[j]);

        const int row = tid + j * TPB;
        #pragma unroll
        for (int k = 0; k < GMM_KP; k++) {
            float f0, f1;
            upk2(num[j][k], f0, f1);
            sStage[row * 17 + 2*k]     = f0 * inv;
            sStage[row * 17 + 2*k + 1] = f1 * inv;
        }
    }
    __syncthreads();
    {
        float* op = out + 1 + (size_t)base * GMM_D;
        const int limit = min(PPB, T - base) * GMM_D;
        for (int i = tid; i < limit; i += TPB)
            op[i] = sStage[(i >> 4) * 17 + (i & 15)];
    }

    // deterministic block reduction of log-likes
    sRed[tid] = llsum;
    __syncthreads();
    #pragma unroll
    for (int s = TPB / 2; s > 0; s >>= 1) {
        if (tid < s) sRed[tid] += sRed[tid + s];
        __syncthreads();
    }
    if (tid == 0) {
        g_part[blockIdx.x] = sRed[0];
        __threadfence();
        unsigned old = atomicAdd(&g_count, 1u);
        sLast = (old == (unsigned)(gridDim.x - 1));
    }
    __syncthreads();

    if (sLast) {
        __threadfence();
        float acc2 = 0.0f;
        for (int i = tid; i < (int)gridDim.x; i += TPB) acc2 += g_part[i];
        sRed[tid] = acc2;
        __syncthreads();
        #pragma unroll
        for (int s = TPB / 2; s > 0; s >>= 1) {
            if (tid < s) sRed[tid] += sRed[tid + s];
            __syncthreads();
        }
        if (tid == 0) {
            out[0] = sRed[0] * invT;
            g_count = 0;
        }
    }
}

extern "C" void kernel_launch(void* const* d_in, const int* in_sizes, int n_in,
                              void* d_out, int out_size) {
    const float* data  = (const float*)d_in[0];
    const float* wghts = (const float*)d_in[1];
    const float* means = (const float*)d_in[2];
    const float* dcovs = (const float*)d_in[3];
    float* out = (float*)d_out;

    const int T = in_sizes[0] / GMM_D;
    const int grid = (T + PPB - 1) / PPB;   // non-persistent: HW backfills

    gmm_precompute<<<1, 1024>>>(wghts, means, dcovs);
    gmm_main<<<grid, TPB>>>(data, means, out, T, 1.0f / (float)T);
}

// round 9
// speedup vs baseline: 1.0776x; 1.0776x over previous
#include <cuda_runtime.h>
#include <cuda_bf16.h>

typedef unsigned long long ull;

#define GMM_M   64
#define GMM_D   16
#define GMM_KP  8      // 16 dims = 8 f32x2 pairs
#define TPB     128
#define PPT     2
#define PPB     (TPB*PPT)

__device__ float4   g_P[GMM_M * GMM_KP];  // {A2k,A2k+1,B2k,B2k+1}, log2e-folded
__device__ float    g_C[GMM_M];           // log2e-folded constant
__device__ float    g_part[8192];
__device__ unsigned g_count = 0;

__device__ __forceinline__ ull pk2(float lo, float hi) {
    ull r; asm("mov.b64 %0, {%1, %2};" : "=l"(r) : "f"(lo), "f"(hi)); return r;
}
__device__ __forceinline__ void upk2(ull v, float &lo, float &hi) {
    asm("mov.b64 {%0, %1}, %2;" : "=f"(lo), "=f"(hi) : "l"(v));
}
__device__ __forceinline__ ull fma2(ull a, ull b, ull c) {
    ull r; asm("fma.rn.f32x2 %0, %1, %2, %3;" : "=l"(r) : "l"(a), "l"(b), "l"(c)); return r;
}
__device__ __forceinline__ ull add2(ull a, ull b) {
    ull r; asm("add.rn.f32x2 %0, %1, %2;" : "=l"(r) : "l"(a), "l"(b)); return r;
}
__device__ __forceinline__ float ex2f(float x) {
    float r; asm("ex2.approx.f32 %0, %1;" : "=f"(r) : "f"(x)); return r;
}

// ---------- kernel 1: parameter precompute (log2e folded) ----------
__global__ void __launch_bounds__(1024)
gmm_precompute(const float* __restrict__ wghts,
               const float* __restrict__ means,
               const float* __restrict__ dcovs) {
    __shared__ float sAf[GMM_M][GMM_D];
    __shared__ float sBf[GMM_M][GMM_D];
    const int tid = threadIdx.x;
    const int m = tid >> 4;
    const int d = tid & 15;
    const float LOG2E = 1.4426950408889634f;

    const float dc   = dcovs[m * GMM_D + d];
    const float mu   = means[m * GMM_D + d];
    const float prec = 1.0f / dc;
    sAf[m][d] = -0.5f * prec * LOG2E;
    sBf[m][d] = prec * mu * LOG2E;

    float cpart = (-0.5f * prec * mu * mu - 0.5f * __logf(dc)) * LOG2E;
    #pragma unroll
    for (int o = 8; o > 0; o >>= 1)
        cpart += __shfl_down_sync(0xffffffffu, cpart, o, 16);
    if (d == 0)
        g_C[m] = cpart + (__logf(wghts[m]) - 8.0f * __logf(6.283185307f)) * LOG2E;

    __syncthreads();
    if (tid < GMM_M * GMM_KP) {
        const int pm = tid >> 3;
        const int k  = tid & 7;
        g_P[tid] = make_float4(sAf[pm][2*k], sAf[pm][2*k+1],
                               sBf[pm][2*k], sBf[pm][2*k+1]);
    }
}

// ---------- kernel 2: main GMM E-step (non-persistent, 5 blocks/SM) ----------
__global__ void __launch_bounds__(TPB, 5)
gmm_main(const float* __restrict__ data,
         const float* __restrict__ means,
         float* __restrict__ out,
         int T, float invT) {
    __shared__ ulonglong2 sP[GMM_M * GMM_KP];
    __shared__ ulonglong2 sMu[GMM_M * 4];
    __shared__ float      sC[GMM_M];
    __shared__ float      sStage[PPB * 17];   // pitch-17 transpose, both points
    __shared__ float      sRed[TPB];
    __shared__ bool       sLast;

    const int tid = threadIdx.x;
    {
        const float4* gp = (const float4*)g_P;
        float4*       dp = (float4*)sP;
        for (int i = tid; i < GMM_M * GMM_KP; i += TPB) dp[i] = gp[i];
        const float4* gm = (const float4*)means;
        float4*       dm = (float4*)sMu;
        for (int i = tid; i < GMM_M * 4; i += TPB) dm[i] = gm[i];
        if (tid < GMM_M) sC[tid] = g_C[tid];
    }
    __syncthreads();

    const int base = blockIdx.x * PPB;

    ull x[PPT][GMM_KP], num[PPT][GMM_KP];
    float like[PPT];

    #pragma unroll
    for (int j = 0; j < PPT; j++) {
        like[j] = 0.0f;
        const int t = base + tid + j * TPB;
        if (t < T) {
            const ulonglong2* dp2 = (const ulonglong2*)(data + (size_t)t * GMM_D);
            #pragma unroll
            for (int q = 0; q < 4; q++) {
                const ulonglong2 f = dp2[q];   // LDG.128, no repack
                x[j][2*q]   = f.x;
                x[j][2*q+1] = f.y;
            }
        } else {
            #pragma unroll
            for (int k = 0; k < GMM_KP; k++) x[j][k] = 0ULL;
        }
        #pragma unroll
        for (int k = 0; k < GMM_KP; k++) num[j][k] = 0ULL;
    }

    #pragma unroll 2
    for (int m = 0; m < GMM_M; m++) {
        // two independent accumulator chains per point (halved critical path)
        ull acc0[PPT], acc1[PPT];
        #pragma unroll
        for (int j = 0; j < PPT; j++) {
            acc0[j] = pk2(sC[m], 0.0f);
            acc1[j] = 0ULL;
        }

        #pragma unroll
        for (int k = 0; k < 4; k++) {
            const ulonglong2 abL = sP[m * GMM_KP + k];       // LDS.128 broadcast
            const ulonglong2 abH = sP[m * GMM_KP + k + 4];
            #pragma unroll
            for (int j = 0; j < PPT; j++) {
                const ull t0 = fma2(abL.x, x[j][k], abL.y);
                acc0[j] = fma2(t0, x[j][k], acc0[j]);
                const ull t1 = fma2(abH.x, x[j][k + 4], abH.y);
                acc1[j] = fma2(t1, x[j][k + 4], acc1[j]);
            }
        }

        ull pb[PPT];
        #pragma unroll
        for (int j = 0; j < PPT; j++) {
            const ull acc = add2(acc0[j], acc1[j]);
            float lo, hi;
            upk2(acc, lo, hi);
            const float p = ex2f(lo + hi);
            like[j] += p;
            pb[j] = pk2(p, p);
        }

        #pragma unroll
        for (int kk = 0; kk < 4; kk++) {
            const ulonglong2 mm = sMu[m * 4 + kk];
            #pragma unroll
            for (int j = 0; j < PPT; j++) {
                num[j][2*kk]   = fma2(pb[j], mm.x, num[j][2*kk]);
                num[j][2*kk+1] = fma2(pb[j], mm.y, num[j][2*kk+1]);
            }
        }
    }

    float llsum = 0.0f;

    // epilogue: single-pass SMEM transpose for both points -> coalesced STG.32
    #pragma unroll
    for (int j = 0; j < PPT; j++) {
        const int tj = base + tid + j * TPB;
        const bool valid = (tj < T);
        const float inv = valid ? __fdividef(1.0f, like[j]) : 0.0f;
        if (valid) llsum += __logf(like[j]);

        const int row = tid + j * TPB;
        #pragma unroll
        for (int k = 0; k < GMM_KP; k++) {
            float f0, f1;
            upk2(num[j][k], f0, f1);
            sStage[row * 17 + 2*k]     = f0 * inv;
            sStage[row * 17 + 2*k + 1] = f1 * inv;
        }
    }
    __syncthreads();
    {
        float* op = out + 1 + (size_t)base * GMM_D;
        const int limit = min(PPB, T - base) * GMM_D;
        for (int i = tid; i < limit; i += TPB)
            op[i] = sStage[(i >> 4) * 17 + (i & 15)];
    }

    // deterministic block reduction of log-likes
    sRed[tid] = llsum;
    __syncthreads();
    #pragma unroll
    for (int s = TPB / 2; s > 0; s >>= 1) {
        if (tid < s) sRed[tid] += sRed[tid + s];
        __syncthreads();
    }
    if (tid == 0) {
        g_part[blockIdx.x] = sRed[0];
        __threadfence();
        unsigned old = atomicAdd(&g_count, 1u);
        sLast = (old == (unsigned)(gridDim.x - 1));
    }
    __syncthreads();

    if (sLast) {
        __threadfence();
        float acc2 = 0.0f;
        for (int i = tid; i < (int)gridDim.x; i += TPB) acc2 += g_part[i];
        sRed[tid] = acc2;
        __syncthreads();
        #pragma unroll
        for (int s = TPB / 2; s > 0; s >>= 1) {
            if (tid < s) sRed[tid] += sRed[tid + s];
            __syncthreads();
        }
        if (tid == 0) {
            out[0] = sRed[0] * invT;
            g_count = 0;
        }
    }
}

extern "C" void kernel_launch(void* const* d_in, const int* in_sizes, int n_in,
                              void* d_out, int out_size) {
    const float* data  = (const float*)d_in[0];
    const float* wghts = (const float*)d_in[1];
    const float* means = (const float*)d_in[2];
    const float* dcovs = (const float*)d_in[3];
    float* out = (float*)d_out;

    const int T = in_sizes[0] / GMM_D;
    const int grid = (T + PPB - 1) / PPB;   // non-persistent: HW backfills

    gmm_precompute<<<1, 1024>>>(wghts, means, dcovs);
    gmm_main<<<grid, TPB>>>(data, means, out, T, 1.0f / (float)T);
}